// round 3
// baseline (speedup 1.0000x reference)
#include <cuda_runtime.h>
#include <cuda_bf16.h>
#include <math.h>

// ---------------- problem constants ----------------
#define BATCH 8
#define SEQ   1024
#define DMODEL 768
#define NHEADS 12
#define DHEAD  64
#define DFF    3072
#define ROWS   (BATCH*SEQ)          // 8192
#define LN_EPS 1e-5f

// ---------------- scratch (static device memory; no allocations) ----------------
__device__ float g_q  [ (size_t)ROWS*DMODEL ];
__device__ float g_k  [ (size_t)ROWS*DMODEL ];
__device__ float g_v  [ (size_t)ROWS*DMODEL ];
__device__ float g_ctx[ (size_t)ROWS*DMODEL ];
__device__ float g_prj[ (size_t)ROWS*DMODEL ];
__device__ float g_ln [ (size_t)ROWS*DMODEL ];
__device__ float g_mid[ (size_t)ROWS*DFF ];
__device__ int   g_mask_mode;   // 0 = uint8, 1 = int32, 2 = float32

// ---------------- mask dtype detection ----------------
__global__ void detect_mask_kernel(const unsigned char* m) {
    if (threadIdx.x != 0) return;
    int c0 = 0, c1 = 0, c2 = 0, c3 = 0;
    for (int i = 0; i < 4096; i += 4) {
        c0 += (m[i]   != 0);
        c1 += (m[i+1] != 0);
        c2 += (m[i+2] != 0);
        c3 += (m[i+3] != 0);
    }
    int mode;
    if (c1 == 0 && c2 == 0 && c3 == 0)      mode = 1;  // int32 0/1: only LSB bytes set
    else if (c0 == 0 && c1 == 0)            mode = 2;  // float32 0.0/1.0: bytes 2,3 set
    else                                     mode = 0;  // uint8 bool
    g_mask_mode = mode;
}

__device__ __forceinline__ bool mask_at(const void* m, size_t idx, int mode) {
    if (mode == 1) return ((const int*)m)[idx]   != 0;
    if (mode == 2) return ((const float*)m)[idx] != 0.0f;
    return ((const unsigned char*)m)[idx] != 0;
}

// ---------------- generic tiled SGEMM:  C[M,N] = A[M,K] @ B[K,N] + bias ----------------
// BM=BN=128, BK=8, 256 threads, 8x8 microtile. M,N multiple of 128; K multiple of 8.
#define BM 128
#define BN 128
#define BK 8

__global__ __launch_bounds__(256, 2)
void gemm_kernel(const float* __restrict__ A, const float* __restrict__ B,
                 const float* __restrict__ bias, float* __restrict__ C,
                 int M, int N, int K, int act) {
    __shared__ float As[BK][BM];
    __shared__ float Bs[BK][BN];

    const int bm = blockIdx.y * BM;
    const int bn = blockIdx.x * BN;
    const int tid = threadIdx.x;
    const int tx = tid & 15;       // 0..15  (n)
    const int ty = tid >> 4;       // 0..15  (m)

    // global-load assignments
    const int a_m = tid >> 1;            // 0..127
    const int a_k = (tid & 1) * 4;       // 0 or 4
    const int b_k = tid >> 5;            // 0..7
    const int b_n = (tid & 31) * 4;      // 0..124

    float acc[8][8];
    #pragma unroll
    for (int i = 0; i < 8; i++)
        #pragma unroll
        for (int j = 0; j < 8; j++) acc[i][j] = 0.0f;

    const float* Aptr = A + (size_t)(bm + a_m) * K + a_k;
    const float* Bptr = B + (size_t)b_k * N + bn + b_n;

    for (int kt = 0; kt < K; kt += BK) {
        float4 av = *(const float4*)(Aptr + kt);
        As[a_k+0][a_m] = av.x;
        As[a_k+1][a_m] = av.y;
        As[a_k+2][a_m] = av.z;
        As[a_k+3][a_m] = av.w;
        *(float4*)&Bs[b_k][b_n] = *(const float4*)(Bptr + (size_t)kt * N);
        __syncthreads();

        #pragma unroll
        for (int kk = 0; kk < BK; kk++) {
            float a[8], b[8];
            *(float4*)(a)     = *(const float4*)&As[kk][ty*8];
            *(float4*)(a + 4) = *(const float4*)&As[kk][ty*8 + 4];
            *(float4*)(b)     = *(const float4*)&Bs[kk][tx*8];
            *(float4*)(b + 4) = *(const float4*)&Bs[kk][tx*8 + 4];
            #pragma unroll
            for (int i = 0; i < 8; i++)
                #pragma unroll
                for (int j = 0; j < 8; j++)
                    acc[i][j] += a[i] * b[j];
        }
        __syncthreads();
    }

    // epilogue: bias + optional exact GELU
    #pragma unroll
    for (int i = 0; i < 8; i++) {
        float* cp = C + (size_t)(bm + ty*8 + i) * N + bn + tx*8;
        float v[8];
        #pragma unroll
        for (int j = 0; j < 8; j++) {
            float x = acc[i][j] + bias[bn + tx*8 + j];
            if (act == 1) x = 0.5f * x * (1.0f + erff(x * 0.70710678118654752f));
            v[j] = x;
        }
        *(float4*)(cp)     = *(float4*)(v);
        *(float4*)(cp + 4) = *(float4*)(v + 4);
    }
}

// ---------------- fused attention: scores -> mask -> softmax -> attn write -> context ----
// Block = (q-tile of 16 rows) x (b,h).  256 threads.
// dyn smem: scores[16][1028] + tile[64][64]
#define TQ 16
#define SC_STRIDE 1028
#define ATTN_SMEM ((TQ*SC_STRIDE + 64*64) * (int)sizeof(float))

__global__ __launch_bounds__(256, 2)
void attn_kernel(const float* __restrict__ q, const float* __restrict__ k,
                 const float* __restrict__ v, const void* __restrict__ mask,
                 float* __restrict__ attn, float* __restrict__ ctx) {
    extern __shared__ float sm[];
    float* scores = sm;                     // TQ * SC_STRIDE
    float* tile   = sm + TQ * SC_STRIDE;    // 64 * 64

    const int qt = blockIdx.x;              // 0..63
    const int bh = blockIdx.y;              // 0..95
    const int b  = bh / NHEADS;
    const int h  = bh % NHEADS;
    const int q0 = qt * TQ;
    const int tid = threadIdx.x;
    const int mode = g_mask_mode;

    // ---- preload this thread's q row (ql = tid&15) into registers ----
    const int ql = tid & 15;
    float4 qreg[16];
    {
        const float* qp = q + (size_t)(b*SEQ + q0 + ql) * DMODEL + h * DHEAD;
        #pragma unroll
        for (int i = 0; i < 16; i++) qreg[i] = ((const float4*)qp)[i];
    }
    const int klb = (tid >> 4) * 4;

    // ---- phase 1: scores = qK^T/8, mask ----
    for (int kt = 0; kt < 16; kt++) {
        // load K tile [64 x 64]
        for (int i4 = tid; i4 < 1024; i4 += 256) {
            int kl = i4 >> 4, dd = (i4 & 15) * 4;
            *(float4*)&tile[kl*64 + dd] =
                *(const float4*)&k[(size_t)(b*SEQ + kt*64 + kl) * DMODEL + h*DHEAD + dd];
        }
        __syncthreads();

        float dot[4] = {0.f, 0.f, 0.f, 0.f};
        #pragma unroll
        for (int d4 = 0; d4 < 16; d4++) {
            float4 qv = qreg[d4];
            #pragma unroll
            for (int kk = 0; kk < 4; kk++) {
                float4 kv = *(const float4*)&tile[(klb + kk)*64 + d4*4];
                dot[kk] += qv.x*kv.x + qv.y*kv.y + qv.z*kv.z + qv.w*kv.w;
            }
        }
        #pragma unroll
        for (int kk = 0; kk < 4; kk++) {
            int kg = kt*64 + klb + kk;
            float s = dot[kk] * 0.125f;  // 1/sqrt(64)
            size_t midx = (size_t)(b*SEQ + q0 + ql) * SEQ + kg;
            if (mask_at(mask, midx, mode)) s = -1e9f;
            scores[ql*SC_STRIDE + kg] = s;
        }
        __syncthreads();
    }

    // ---- phase 2: softmax per row (16 threads / row) ----
    {
        const int r = tid >> 4;
        const int t = tid & 15;
        float* row = &scores[r * SC_STRIDE];
        float mx = -3.4e38f;
        for (int j = t; j < SEQ; j += 16) mx = fmaxf(mx, row[j]);
        #pragma unroll
        for (int m = 8; m; m >>= 1) mx = fmaxf(mx, __shfl_xor_sync(0xffffffffu, mx, m));
        float sum = 0.f;
        for (int j = t; j < SEQ; j += 16) {
            float e = __expf(row[j] - mx);
            row[j] = e;
            sum += e;
        }
        #pragma unroll
        for (int m = 8; m; m >>= 1) sum += __shfl_xor_sync(0xffffffffu, sum, m);
        float inv = 1.0f / sum;
        for (int j = t; j < SEQ; j += 16) row[j] *= inv;
    }
    __syncthreads();

    // ---- write attn rows (coalesced) ----
    if (attn != nullptr) {
        float* dst = attn + ((size_t)(b*NHEADS + h) * SEQ + q0) * SEQ;
        for (int i4 = tid; i4 < TQ * SEQ / 4; i4 += 256) {
            int r = i4 >> 8, c4 = i4 & 255;
            ((float4*)dst)[i4] = *(const float4*)&scores[r*SC_STRIDE + c4*4];
        }
    }

    // ---- phase 3: context = attn @ V ----
    const int ql3 = tid >> 4;
    const int dq  = (tid & 15) * 4;
    float4 acc = make_float4(0.f, 0.f, 0.f, 0.f);
    for (int vt = 0; vt < 16; vt++) {
        __syncthreads();
        for (int i4 = tid; i4 < 1024; i4 += 256) {
            int kl = i4 >> 4, dd = (i4 & 15) * 4;
            *(float4*)&tile[kl*64 + dd] =
                *(const float4*)&v[(size_t)(b*SEQ + vt*64 + kl) * DMODEL + h*DHEAD + dd];
        }
        __syncthreads();
        const float* srow = &scores[ql3*SC_STRIDE + vt*64];
        #pragma unroll 8
        for (int kl = 0; kl < 64; kl++) {
            float s = srow[kl];
            float4 vv = *(const float4*)&tile[kl*64 + dq];
            acc.x += s*vv.x; acc.y += s*vv.y; acc.z += s*vv.z; acc.w += s*vv.w;
        }
    }
    *(float4*)&ctx[(size_t)(b*SEQ + q0 + ql3) * DMODEL + h*DHEAD + dq] = acc;
}

// ---------------- residual + LayerNorm ----------------
__global__ __launch_bounds__(256)
void ln_kernel(const float* __restrict__ proj, const float* __restrict__ x,
               const float* __restrict__ gamma, const float* __restrict__ beta,
               float* __restrict__ out) {
    const int row = blockIdx.x;
    const float* p  = proj + (size_t)row * DMODEL;
    const float* xr = x    + (size_t)row * DMODEL;
    float s = 0.f, s2 = 0.f;
    for (int i = threadIdx.x; i < DMODEL; i += 256) {
        float v = p[i] + xr[i];
        s += v; s2 += v*v;
    }
    #pragma unroll
    for (int m = 16; m; m >>= 1) {
        s  += __shfl_xor_sync(0xffffffffu, s,  m);
        s2 += __shfl_xor_sync(0xffffffffu, s2, m);
    }
    __shared__ float ws[8], ws2[8];
    int w = threadIdx.x >> 5, l = threadIdx.x & 31;
    if (l == 0) { ws[w] = s; ws2[w] = s2; }
    __syncthreads();
    __shared__ float smu, srstd;
    if (threadIdx.x == 0) {
        float ts = 0.f, ts2 = 0.f;
        for (int i = 0; i < 8; i++) { ts += ws[i]; ts2 += ws2[i]; }
        float mu  = ts  * (1.0f/DMODEL);
        float var = ts2 * (1.0f/DMODEL) - mu*mu;
        smu = mu; srstd = rsqrtf(var + LN_EPS);
    }
    __syncthreads();
    float mu = smu, r = srstd;
    float* o = out + (size_t)row * DMODEL;
    for (int i = threadIdx.x; i < DMODEL; i += 256)
        o[i] = (p[i] + xr[i] - mu) * r * gamma[i] + beta[i];
}

// ---------------- launcher ----------------
extern "C" void kernel_launch(void* const* d_in, const int* in_sizes, int n_in,
                              void* d_out, int out_size) {
    const float* x     = (const float*)d_in[0];
    const void*  mask  = d_in[1];
    const float* Wq    = (const float*)d_in[2];
    const float* bq    = (const float*)d_in[3];
    const float* Wk    = (const float*)d_in[4];
    const float* bk    = (const float*)d_in[5];
    const float* Wv    = (const float*)d_in[6];
    const float* bv    = (const float*)d_in[7];
    const float* Wo    = (const float*)d_in[8];
    const float* bo    = (const float*)d_in[9];
    const float* gamma = (const float*)d_in[10];
    const float* beta  = (const float*)d_in[11];
    const float* W1    = (const float*)d_in[12];
    const float* b1    = (const float*)d_in[13];
    const float* W2    = (const float*)d_in[14];
    const float* b2    = (const float*)d_in[15];

    float* out = (float*)d_out;
    const long long FFN_E  = (long long)ROWS * DMODEL;                 //   6,291,456
    const long long ATTN_E = (long long)BATCH * NHEADS * SEQ * SEQ;    // 100,663,296
    float* attn = ((long long)out_size >= FFN_E + ATTN_E) ? (out + FFN_E) : nullptr;

    float *q, *k, *v, *ctx, *prj, *ln, *mid;
    cudaGetSymbolAddress((void**)&q,   g_q);
    cudaGetSymbolAddress((void**)&k,   g_k);
    cudaGetSymbolAddress((void**)&v,   g_v);
    cudaGetSymbolAddress((void**)&ctx, g_ctx);
    cudaGetSymbolAddress((void**)&prj, g_prj);
    cudaGetSymbolAddress((void**)&ln,  g_ln);
    cudaGetSymbolAddress((void**)&mid, g_mid);

    cudaFuncSetAttribute(attn_kernel, cudaFuncAttributeMaxDynamicSharedMemorySize, ATTN_SMEM);

    detect_mask_kernel<<<1, 32>>>((const unsigned char*)mask);

    dim3 gQKV(DMODEL / BN, ROWS / BM);         // (6, 64)
    gemm_kernel<<<gQKV, 256>>>(x, Wq, bq, q, ROWS, DMODEL, DMODEL, 0);
    gemm_kernel<<<gQKV, 256>>>(x, Wk, bk, k, ROWS, DMODEL, DMODEL, 0);
    gemm_kernel<<<gQKV, 256>>>(x, Wv, bv, v, ROWS, DMODEL, DMODEL, 0);

    attn_kernel<<<dim3(SEQ / TQ, BATCH * NHEADS), 256, ATTN_SMEM>>>(q, k, v, mask, attn, ctx);

    gemm_kernel<<<gQKV, 256>>>(ctx, Wo, bo, prj, ROWS, DMODEL, DMODEL, 0);
    ln_kernel<<<ROWS, 256>>>(prj, x, gamma, beta, ln);

    dim3 gF1(DFF / BN, ROWS / BM);             // (24, 64)
    gemm_kernel<<<gF1, 256>>>(ln, W1, b1, mid, ROWS, DFF, DMODEL, 1);

    dim3 gF2(DMODEL / BN, ROWS / BM);          // (6, 64)
    gemm_kernel<<<gF2, 256>>>(mid, W2, b2, out, ROWS, DMODEL, DFF, 0);
}

// round 4
// speedup vs baseline: 1.5568x; 1.5568x over previous
#include <cuda_runtime.h>
#include <cuda_bf16.h>
#include <math.h>
#include <stdint.h>

// ---------------- problem constants ----------------
#define BATCH 8
#define SEQ   1024
#define DMODEL 768
#define NHEADS 12
#define DHEAD  64
#define DFF    3072
#define ROWS   (BATCH*SEQ)          // 8192
#define LN_EPS 1e-5f

// ---------------- scratch (static device memory; no allocations) ----------------
__device__ float g_q  [ (size_t)ROWS*DMODEL ];
__device__ float g_k  [ (size_t)ROWS*DMODEL ];
__device__ float g_v  [ (size_t)ROWS*DMODEL ];
__device__ float g_ctx[ (size_t)ROWS*DMODEL ];
__device__ float g_prj[ (size_t)ROWS*DMODEL ];
__device__ float g_ln [ (size_t)ROWS*DMODEL ];
__device__ float g_mid[ (size_t)ROWS*DFF ];
__device__ int   g_mask_mode;   // 0 = uint8, 1 = int32, 2 = float32

// ---------------- mask dtype detection ----------------
__global__ void detect_mask_kernel(const unsigned char* m) {
    if (threadIdx.x != 0) return;
    int c0 = 0, c1 = 0, c2 = 0, c3 = 0;
    for (int i = 0; i < 4096; i += 4) {
        c0 += (m[i]   != 0);
        c1 += (m[i+1] != 0);
        c2 += (m[i+2] != 0);
        c3 += (m[i+3] != 0);
    }
    int mode;
    if (c1 == 0 && c2 == 0 && c3 == 0)      mode = 1;  // int32 0/1: only LSB bytes set
    else if (c0 == 0 && c1 == 0)            mode = 2;  // float32 0.0/1.0: bytes 2,3 set
    else                                     mode = 0;  // uint8 bool
    g_mask_mode = mode;
}

__device__ __forceinline__ bool mask_at(const void* m, size_t idx, int mode) {
    if (mode == 1) return ((const int*)m)[idx]   != 0;
    if (mode == 2) return ((const float*)m)[idx] != 0.0f;
    return ((const unsigned char*)m)[idx] != 0;
}

// ================= tf32 tensor-core GEMM =================
// C[M,N] = A[M,K] @ B[K,N] + bias (+ exact GELU if act==1)
// BM=BN=128, BK=16, 256 threads (8 warps), warp tile 64x32 via 4x4 m16n8k8 mmas.
#define BM 128
#define BN 128
#define BK 16
#define SMS 132   // smem row stride (conflict-free fragment loads)

__device__ __forceinline__ uint32_t f2tf32(float x) {
    uint32_t r;
    asm("cvt.rna.tf32.f32 %0, %1;" : "=r"(r) : "f"(x));
    return r;
}

__device__ __forceinline__ void mma_tf32(float* c, const uint32_t* a, const uint32_t* b) {
    asm volatile(
        "mma.sync.aligned.m16n8k8.row.col.f32.tf32.tf32.f32 "
        "{%0,%1,%2,%3}, {%4,%5,%6,%7}, {%8,%9}, {%0,%1,%2,%3};"
        : "+f"(c[0]), "+f"(c[1]), "+f"(c[2]), "+f"(c[3])
        : "r"(a[0]), "r"(a[1]), "r"(a[2]), "r"(a[3]), "r"(b[0]), "r"(b[1]));
}

__global__ __launch_bounds__(256)
void gemm_tf32_kernel(const float* __restrict__ A, const float* __restrict__ B,
                      const float* __restrict__ bias, float* __restrict__ C,
                      int M, int N, int K, int act) {
    __shared__ float As[BK][SMS];   // [k][m], tf32-rounded values
    __shared__ float Bs[BK][SMS];   // [k][n], tf32-rounded values

    const int tid  = threadIdx.x;
    const int warp = tid >> 5;
    const int lane = tid & 31;
    const int grp  = lane >> 2;     // 0..7
    const int thr  = lane & 3;      // 0..3
    const int wm   = warp >> 2;     // 0..1 -> m offset wm*64
    const int wn   = warp & 3;      // 0..3 -> n offset wn*32
    const int bm   = blockIdx.y * BM;
    const int bn   = blockIdx.x * BN;

    // global load mapping
    const int a_row = tid >> 1;          // 0..127
    const int a_k   = (tid & 1) * 8;     // 0 or 8
    const int b_row = tid >> 4;          // 0..15 (k)
    const int b_col = (tid & 15) * 8;    // 0..120

    const float* Ap = A + (size_t)(bm + a_row) * K + a_k;
    const float* Bp = B + (size_t)b_row * N + bn + b_col;

    float acc[4][4][4];
    #pragma unroll
    for (int mi = 0; mi < 4; mi++)
        #pragma unroll
        for (int ni = 0; ni < 4; ni++)
            #pragma unroll
            for (int j = 0; j < 4; j++) acc[mi][ni][j] = 0.0f;

    // ---- preload tile 0 ----
    {
        float4 a0 = *(const float4*)(Ap);
        float4 a1 = *(const float4*)(Ap + 4);
        float4 b0 = *(const float4*)(Bp);
        float4 b1 = *(const float4*)(Bp + 4);
        As[a_k+0][a_row] = __uint_as_float(f2tf32(a0.x));
        As[a_k+1][a_row] = __uint_as_float(f2tf32(a0.y));
        As[a_k+2][a_row] = __uint_as_float(f2tf32(a0.z));
        As[a_k+3][a_row] = __uint_as_float(f2tf32(a0.w));
        As[a_k+4][a_row] = __uint_as_float(f2tf32(a1.x));
        As[a_k+5][a_row] = __uint_as_float(f2tf32(a1.y));
        As[a_k+6][a_row] = __uint_as_float(f2tf32(a1.z));
        As[a_k+7][a_row] = __uint_as_float(f2tf32(a1.w));
        Bs[b_row][b_col+0] = __uint_as_float(f2tf32(b0.x));
        Bs[b_row][b_col+1] = __uint_as_float(f2tf32(b0.y));
        Bs[b_row][b_col+2] = __uint_as_float(f2tf32(b0.z));
        Bs[b_row][b_col+3] = __uint_as_float(f2tf32(b0.w));
        Bs[b_row][b_col+4] = __uint_as_float(f2tf32(b1.x));
        Bs[b_row][b_col+5] = __uint_as_float(f2tf32(b1.y));
        Bs[b_row][b_col+6] = __uint_as_float(f2tf32(b1.z));
        Bs[b_row][b_col+7] = __uint_as_float(f2tf32(b1.w));
    }
    __syncthreads();

    for (int kt = 0; kt < K; kt += BK) {
        const bool has_next = (kt + BK < K);
        float4 pa0, pa1, pb0, pb1;
        if (has_next) {
            pa0 = *(const float4*)(Ap + kt + BK);
            pa1 = *(const float4*)(Ap + kt + BK + 4);
            pb0 = *(const float4*)(Bp + (size_t)(kt + BK) * N);
            pb1 = *(const float4*)(Bp + (size_t)(kt + BK) * N + 4);
        }

        // ---- compute on current smem tile: two k-steps of 8 ----
        #pragma unroll
        for (int kk = 0; kk < BK; kk += 8) {
            uint32_t afr[4][4];
            #pragma unroll
            for (int mi = 0; mi < 4; mi++) {
                int m0 = wm*64 + mi*16 + grp;
                afr[mi][0] = __float_as_uint(As[kk + thr    ][m0    ]);
                afr[mi][1] = __float_as_uint(As[kk + thr    ][m0 + 8]);
                afr[mi][2] = __float_as_uint(As[kk + thr + 4][m0    ]);
                afr[mi][3] = __float_as_uint(As[kk + thr + 4][m0 + 8]);
            }
            uint32_t bfr[4][2];
            #pragma unroll
            for (int ni = 0; ni < 4; ni++) {
                int n0 = wn*32 + ni*8 + grp;
                bfr[ni][0] = __float_as_uint(Bs[kk + thr    ][n0]);
                bfr[ni][1] = __float_as_uint(Bs[kk + thr + 4][n0]);
            }
            #pragma unroll
            for (int mi = 0; mi < 4; mi++)
                #pragma unroll
                for (int ni = 0; ni < 4; ni++)
                    mma_tf32(acc[mi][ni], afr[mi], bfr[ni]);
        }
        __syncthreads();

        if (has_next) {
            As[a_k+0][a_row] = __uint_as_float(f2tf32(pa0.x));
            As[a_k+1][a_row] = __uint_as_float(f2tf32(pa0.y));
            As[a_k+2][a_row] = __uint_as_float(f2tf32(pa0.z));
            As[a_k+3][a_row] = __uint_as_float(f2tf32(pa0.w));
            As[a_k+4][a_row] = __uint_as_float(f2tf32(pa1.x));
            As[a_k+5][a_row] = __uint_as_float(f2tf32(pa1.y));
            As[a_k+6][a_row] = __uint_as_float(f2tf32(pa1.z));
            As[a_k+7][a_row] = __uint_as_float(f2tf32(pa1.w));
            Bs[b_row][b_col+0] = __uint_as_float(f2tf32(pb0.x));
            Bs[b_row][b_col+1] = __uint_as_float(f2tf32(pb0.y));
            Bs[b_row][b_col+2] = __uint_as_float(f2tf32(pb0.z));
            Bs[b_row][b_col+3] = __uint_as_float(f2tf32(pb0.w));
            Bs[b_row][b_col+4] = __uint_as_float(f2tf32(pb1.x));
            Bs[b_row][b_col+5] = __uint_as_float(f2tf32(pb1.y));
            Bs[b_row][b_col+6] = __uint_as_float(f2tf32(pb1.z));
            Bs[b_row][b_col+7] = __uint_as_float(f2tf32(pb1.w));
            __syncthreads();
        }
    }

    // ---- epilogue: bias + optional exact GELU ----
    #pragma unroll
    for (int mi = 0; mi < 4; mi++) {
        #pragma unroll
        for (int ni = 0; ni < 4; ni++) {
            int row0 = bm + wm*64 + mi*16 + grp;
            int col  = bn + wn*32 + ni*8 + 2*thr;
            float bz0 = bias[col], bz1 = bias[col + 1];
            float v0 = acc[mi][ni][0] + bz0;
            float v1 = acc[mi][ni][1] + bz1;
            float v2 = acc[mi][ni][2] + bz0;
            float v3 = acc[mi][ni][3] + bz1;
            if (act == 1) {
                v0 = 0.5f * v0 * (1.0f + erff(v0 * 0.70710678118654752f));
                v1 = 0.5f * v1 * (1.0f + erff(v1 * 0.70710678118654752f));
                v2 = 0.5f * v2 * (1.0f + erff(v2 * 0.70710678118654752f));
                v3 = 0.5f * v3 * (1.0f + erff(v3 * 0.70710678118654752f));
            }
            *(float2*)(C + (size_t)row0 * N + col)       = make_float2(v0, v1);
            *(float2*)(C + (size_t)(row0 + 8) * N + col) = make_float2(v2, v3);
        }
    }
}

// ---------------- fused attention: scores -> mask -> softmax -> attn write -> context ----
#define TQ 16
#define SC_STRIDE 1028
#define ATTN_SMEM ((TQ*SC_STRIDE + 64*64) * (int)sizeof(float))

__global__ __launch_bounds__(256, 2)
void attn_kernel(const float* __restrict__ q, const float* __restrict__ k,
                 const float* __restrict__ v, const void* __restrict__ mask,
                 float* __restrict__ attn, float* __restrict__ ctx) {
    extern __shared__ float sm[];
    float* scores = sm;                     // TQ * SC_STRIDE
    float* tile   = sm + TQ * SC_STRIDE;    // 64 * 64

    const int qt = blockIdx.x;              // 0..63
    const int bh = blockIdx.y;              // 0..95
    const int b  = bh / NHEADS;
    const int h  = bh % NHEADS;
    const int q0 = qt * TQ;
    const int tid = threadIdx.x;
    const int mode = g_mask_mode;

    const int ql = tid & 15;
    float4 qreg[16];
    {
        const float* qp = q + (size_t)(b*SEQ + q0 + ql) * DMODEL + h * DHEAD;
        #pragma unroll
        for (int i = 0; i < 16; i++) qreg[i] = ((const float4*)qp)[i];
    }
    const int klb = (tid >> 4) * 4;

    // ---- phase 1: scores = qK^T/8, mask ----
    for (int kt = 0; kt < 16; kt++) {
        for (int i4 = tid; i4 < 1024; i4 += 256) {
            int kl = i4 >> 4, dd = (i4 & 15) * 4;
            *(float4*)&tile[kl*64 + dd] =
                *(const float4*)&k[(size_t)(b*SEQ + kt*64 + kl) * DMODEL + h*DHEAD + dd];
        }
        __syncthreads();

        float dot[4] = {0.f, 0.f, 0.f, 0.f};
        #pragma unroll
        for (int d4 = 0; d4 < 16; d4++) {
            float4 qv = qreg[d4];
            #pragma unroll
            for (int kk = 0; kk < 4; kk++) {
                float4 kv = *(const float4*)&tile[(klb + kk)*64 + d4*4];
                dot[kk] += qv.x*kv.x + qv.y*kv.y + qv.z*kv.z + qv.w*kv.w;
            }
        }
        #pragma unroll
        for (int kk = 0; kk < 4; kk++) {
            int kg = kt*64 + klb + kk;
            float s = dot[kk] * 0.125f;  // 1/sqrt(64)
            size_t midx = (size_t)(b*SEQ + q0 + ql) * SEQ + kg;
            if (mask_at(mask, midx, mode)) s = -1e9f;
            scores[ql*SC_STRIDE + kg] = s;
        }
        __syncthreads();
    }

    // ---- phase 2: softmax per row (16 threads / row) ----
    {
        const int r = tid >> 4;
        const int t = tid & 15;
        float* row = &scores[r * SC_STRIDE];
        float mx = -3.4e38f;
        for (int j = t; j < SEQ; j += 16) mx = fmaxf(mx, row[j]);
        #pragma unroll
        for (int m = 8; m; m >>= 1) mx = fmaxf(mx, __shfl_xor_sync(0xffffffffu, mx, m));
        float sum = 0.f;
        for (int j = t; j < SEQ; j += 16) {
            float e = __expf(row[j] - mx);
            row[j] = e;
            sum += e;
        }
        #pragma unroll
        for (int m = 8; m; m >>= 1) sum += __shfl_xor_sync(0xffffffffu, sum, m);
        float inv = 1.0f / sum;
        for (int j = t; j < SEQ; j += 16) row[j] *= inv;
    }
    __syncthreads();

    // ---- write attn rows (coalesced) ----
    if (attn != nullptr) {
        float* dst = attn + ((size_t)(b*NHEADS + h) * SEQ + q0) * SEQ;
        for (int i4 = tid; i4 < TQ * SEQ / 4; i4 += 256) {
            int r = i4 >> 8, c4 = i4 & 255;
            ((float4*)dst)[i4] = *(const float4*)&scores[r*SC_STRIDE + c4*4];
        }
    }

    // ---- phase 3: context = attn @ V ----
    const int ql3 = tid >> 4;
    const int dq  = (tid & 15) * 4;
    float4 acc = make_float4(0.f, 0.f, 0.f, 0.f);
    for (int vt = 0; vt < 16; vt++) {
        __syncthreads();
        for (int i4 = tid; i4 < 1024; i4 += 256) {
            int kl = i4 >> 4, dd = (i4 & 15) * 4;
            *(float4*)&tile[kl*64 + dd] =
                *(const float4*)&v[(size_t)(b*SEQ + vt*64 + kl) * DMODEL + h*DHEAD + dd];
        }
        __syncthreads();
        const float* srow = &scores[ql3*SC_STRIDE + vt*64];
        #pragma unroll 8
        for (int kl = 0; kl < 64; kl++) {
            float s = srow[kl];
            float4 vv = *(const float4*)&tile[kl*64 + dq];
            acc.x += s*vv.x; acc.y += s*vv.y; acc.z += s*vv.z; acc.w += s*vv.w;
        }
    }
    *(float4*)&ctx[(size_t)(b*SEQ + q0 + ql3) * DMODEL + h*DHEAD + dq] = acc;
}

// ---------------- residual + LayerNorm ----------------
__global__ __launch_bounds__(256)
void ln_kernel(const float* __restrict__ proj, const float* __restrict__ x,
               const float* __restrict__ gamma, const float* __restrict__ beta,
               float* __restrict__ out) {
    const int row = blockIdx.x;
    const float* p  = proj + (size_t)row * DMODEL;
    const float* xr = x    + (size_t)row * DMODEL;
    float s = 0.f, s2 = 0.f;
    for (int i = threadIdx.x; i < DMODEL; i += 256) {
        float v = p[i] + xr[i];
        s += v; s2 += v*v;
    }
    #pragma unroll
    for (int m = 16; m; m >>= 1) {
        s  += __shfl_xor_sync(0xffffffffu, s,  m);
        s2 += __shfl_xor_sync(0xffffffffu, s2, m);
    }
    __shared__ float ws[8], ws2[8];
    int w = threadIdx.x >> 5, l = threadIdx.x & 31;
    if (l == 0) { ws[w] = s; ws2[w] = s2; }
    __syncthreads();
    __shared__ float smu, srstd;
    if (threadIdx.x == 0) {
        float ts = 0.f, ts2 = 0.f;
        for (int i = 0; i < 8; i++) { ts += ws[i]; ts2 += ws2[i]; }
        float mu  = ts  * (1.0f/DMODEL);
        float var = ts2 * (1.0f/DMODEL) - mu*mu;
        smu = mu; srstd = rsqrtf(var + LN_EPS);
    }
    __syncthreads();
    float mu = smu, r = srstd;
    float* o = out + (size_t)row * DMODEL;
    for (int i = threadIdx.x; i < DMODEL; i += 256)
        o[i] = (p[i] + xr[i] - mu) * r * gamma[i] + beta[i];
}

// ---------------- launcher ----------------
extern "C" void kernel_launch(void* const* d_in, const int* in_sizes, int n_in,
                              void* d_out, int out_size) {
    const float* x     = (const float*)d_in[0];
    const void*  mask  = d_in[1];
    const float* Wq    = (const float*)d_in[2];
    const float* bq    = (const float*)d_in[3];
    const float* Wk    = (const float*)d_in[4];
    const float* bk    = (const float*)d_in[5];
    const float* Wv    = (const float*)d_in[6];
    const float* bv    = (const float*)d_in[7];
    const float* Wo    = (const float*)d_in[8];
    const float* bo    = (const float*)d_in[9];
    const float* gamma = (const float*)d_in[10];
    const float* beta  = (const float*)d_in[11];
    const float* W1    = (const float*)d_in[12];
    const float* b1    = (const float*)d_in[13];
    const float* W2    = (const float*)d_in[14];
    const float* b2    = (const float*)d_in[15];

    float* out = (float*)d_out;
    const long long FFN_E  = (long long)ROWS * DMODEL;                 //   6,291,456
    const long long ATTN_E = (long long)BATCH * NHEADS * SEQ * SEQ;    // 100,663,296
    float* attn = ((long long)out_size >= FFN_E + ATTN_E) ? (out + FFN_E) : nullptr;

    float *q, *k, *v, *ctx, *prj, *ln, *mid;
    cudaGetSymbolAddress((void**)&q,   g_q);
    cudaGetSymbolAddress((void**)&k,   g_k);
    cudaGetSymbolAddress((void**)&v,   g_v);
    cudaGetSymbolAddress((void**)&ctx, g_ctx);
    cudaGetSymbolAddress((void**)&prj, g_prj);
    cudaGetSymbolAddress((void**)&ln,  g_ln);
    cudaGetSymbolAddress((void**)&mid, g_mid);

    cudaFuncSetAttribute(attn_kernel, cudaFuncAttributeMaxDynamicSharedMemorySize, ATTN_SMEM);

    detect_mask_kernel<<<1, 32>>>((const unsigned char*)mask);

    dim3 gQKV(DMODEL / BN, ROWS / BM);         // (6, 64)
    gemm_tf32_kernel<<<gQKV, 256>>>(x, Wq, bq, q, ROWS, DMODEL, DMODEL, 0);
    gemm_tf32_kernel<<<gQKV, 256>>>(x, Wk, bk, k, ROWS, DMODEL, DMODEL, 0);
    gemm_tf32_kernel<<<gQKV, 256>>>(x, Wv, bv, v, ROWS, DMODEL, DMODEL, 0);

    attn_kernel<<<dim3(SEQ / TQ, BATCH * NHEADS), 256, ATTN_SMEM>>>(q, k, v, mask, attn, ctx);

    gemm_tf32_kernel<<<gQKV, 256>>>(ctx, Wo, bo, prj, ROWS, DMODEL, DMODEL, 0);
    ln_kernel<<<ROWS, 256>>>(prj, x, gamma, beta, ln);

    dim3 gF1(DFF / BN, ROWS / BM);             // (24, 64)
    gemm_tf32_kernel<<<gF1, 256>>>(ln, W1, b1, mid, ROWS, DFF, DMODEL, 1);

    dim3 gF2(DMODEL / BN, ROWS / BM);          // (6, 64)
    gemm_tf32_kernel<<<gF2, 256>>>(mid, W2, b2, out, ROWS, DMODEL, DFF, 0);
}